// round 14
// baseline (speedup 1.0000x reference)
#include <cuda_runtime.h>

#define NUM_CLS   8
#define MAX_INST  64
#define NB        32            // batch
#define HW        (1024*1024)   // pixels per sample
#define HT        256           // threads per block
#define CHUNKS    32            // blocks per sample along pixel dim
#define GRID      (NB * CHUNKS)

__device__ __align__(16) int g_inst_sizes[NB * MAX_INST];  // static-zero; reset each run
__device__ unsigned int g_done;                            // static-zero; reset each run

// Fused kernel: per-block 64-bin histogram with CONFLICT-FREE packed-u8
// private counters (word w = bin&15 holds bins w, w+16, w+32, w+48 in its
// bytes; bank = tid%32 independent of data; max 128 elems/thread -> u8 safe).
// Mainloop is software-pipelined (double-buffered batch-2 int4 loads) so
// LDGs stay in flight WHILE the increment chain issues -> DRAM/issue overlap.
__global__ __launch_bounds__(HT, 8) void fused_kernel(const int*   __restrict__ mask,
                                                      const float* __restrict__ pred,
                                                      const int*   __restrict__ label_raw,
                                                      float*       __restrict__ out) {
    __shared__ __align__(16) unsigned int cnt32[16 * HT];   // 16 KB, reused in tail
    __shared__ int binsum[MAX_INST];
    __shared__ unsigned int s_ticket;

    const int tid = threadIdx.x;

    #pragma unroll
    for (int i = tid; i < 16 * HT; i += HT) cnt32[i] = 0u;
    if (tid < MAX_INST) binsum[tid] = 0;
    __syncthreads();

    const int sample = blockIdx.y;
    const int chunk  = blockIdx.x;
    const int elems  = HW / CHUNKS;     // 32768 per block

    const int4* __restrict__ p =
        (const int4*)(mask + (size_t)sample * HW + (size_t)chunk * elems) + tid;

    // bank = tid%32 always: no conflicts for any bin pattern.
#define INC(v) { unsigned int _u = (unsigned int)(v);                          \
                 cnt32[((_u & 15u) << 8) + tid] += 1u << ((_u & 48u) >> 1); }

    // 32 int4/thread = 16 pipelined iterations of batch-2.
    int4 a = p[0 * HT];
    int4 b = p[1 * HT];
    p += 2 * HT;
    #pragma unroll 1
    for (int it = 0; it < 15; it++) {
        int4 a2 = p[0 * HT];            // prefetch next batch BEFORE consuming
        int4 b2 = p[1 * HT];
        p += 2 * HT;
        INC(a.x); INC(a.y); INC(a.z); INC(a.w);
        INC(b.x); INC(b.y); INC(b.z); INC(b.w);
        a = a2; b = b2;
    }
    INC(a.x); INC(a.y); INC(a.z); INC(a.w);
    INC(b.x); INC(b.y); INC(b.z); INC(b.w);
#undef INC
    __syncthreads();

    // Reduce: word column w (16 cols x 256 slots); 16 threads per column
    // (j = tid>>4), each sums 16 staggered slots -> conflict-free LDS.
    // Packed pair accumulators: sA holds bins w (lo16) / w+32 (hi16),
    // sB holds w+16 / w+48. Max per half = 16*128 < 65536, no overflow.
    {
        const int w = tid & 15;
        const int j = tid >> 4;
        unsigned int sA = 0, sB = 0;
        #pragma unroll
        for (int i = 0; i < 16; i++) {
            unsigned int v = cnt32[(w << 8) + j * 16 + ((i + tid) & 15)];
            sA += v & 0x00FF00FFu;
            sB += (v >> 8) & 0x00FF00FFu;
        }
        atomicAdd(&binsum[w],      (int)(sA & 0xFFFFu));
        atomicAdd(&binsum[w + 16], (int)(sB & 0xFFFFu));
        atomicAdd(&binsum[w + 32], (int)(sA >> 16));
        atomicAdd(&binsum[w + 48], (int)(sB >> 16));
    }
    __syncthreads();
    if (tid < MAX_INST)
        atomicAdd(&g_inst_sizes[sample * MAX_INST + tid], binsum[tid]);

    // ---- last-block-done handoff ----
    __threadfence();
    __syncthreads();
    if (tid == 0) s_ticket = atomicAdd(&g_done, 1u);
    __syncthreads();
    if (s_ticket != GRID - 1) return;

    // ================= last block: loss computation =================
    __threadfence();                       // acquire: see all blocks' bin atomics

    int*   isz   = (int*)cnt32;            // [2048] totals (8 KB, fits in 16 KB)
    int*   cnts  = isz + NB * MAX_INST;    // [256] per-class pixel counts
    float* red   = (float*)(cnts + NB * NUM_CLS);
    int*   flags = (int*)(red + 8);

    for (int i = tid; i < NB * MAX_INST / 4; i += HT)
        ((int4*)isz)[i] = ((const int4*)g_inst_sizes)[i];     // L2-hot, 8 KB
    if (tid == 0) flags[0] = 0;
    if (tid < NB * NUM_CLS) cnts[tid] = 0;
    __syncthreads();

    // Reset globals for the next graph replay.
    for (int i = tid; i < NB * MAX_INST / 4; i += HT)
        ((int4*)g_inst_sizes)[i] = make_int4(0, 0, 0, 0);
    if (tid == 0) g_done = 0u;

    // int64-vs-int32 layout detection: values < 32, so little-endian int64
    // means every odd 32-bit word of the first 64 values is 0.
    if (tid < 64) {
        if (label_raw[2 * tid + 1] != 0) atomicOr(&flags[0], 1);
    }
    __syncthreads();

    const int is64 = !flags[0];
    for (int q = tid; q < NB * 64; q += HT) {
        int b = q >> 6;
        int id, lbl;
        if (is64) { id = label_raw[4 * q]; lbl = label_raw[4 * q + 2]; }
        else      { id = label_raw[2 * q]; lbl = label_raw[2 * q + 1]; }
        if (lbl > 0 && lbl <= NUM_CLS)
            atomicAdd(&cnts[b * NUM_CLS + lbl - 1], isz[b * MAX_INST + (id & (MAX_INST - 1))]);
    }
    __syncthreads();

    float term = 0.0f;
    if (tid < NB * NUM_CLS) {
        float x  = pred[tid];
        float cl = fminf((float)cnts[tid] * (1.0f / 100.0f), 1.0f);
        term = fmaxf(x, 0.0f) - x * cl + log1pf(expf(-fabsf(x)));
    }
    #pragma unroll
    for (int o = 16; o; o >>= 1) term += __shfl_down_sync(0xffffffffu, term, o);
    if ((tid & 31) == 0) red[tid >> 5] = term;
    __syncthreads();
    if (tid < 8) {
        float sr = red[tid];
        #pragma unroll
        for (int o = 4; o; o >>= 1) sr += __shfl_down_sync(0xffu, sr, o);
        if (tid == 0) out[0] = sr * (1.0f / (float)(NB * NUM_CLS));
    }
}

// ---------------- launch ----------------
extern "C" void kernel_launch(void* const* d_in, const int* in_sizes, int n_in,
                              void* d_out, int out_size) {
    const float* pred  = (const float*)d_in[0];          // [32, 8] f32
    const int*   mask  = (const int*)d_in[1];            // [32, 1024, 1024] i32
    const int*   label = (const int*)d_in[2];            // [32, 64, 2] i32 or i64
    float*       out   = (float*)d_out;

    dim3 grid(CHUNKS, NB);
    fused_kernel<<<grid, HT>>>(mask, pred, label, out);
}